// round 2
// baseline (speedup 1.0000x reference)
#include <cuda_runtime.h>
#include <cuda_bf16.h>
#include <cstdint>
#include <cstddef>

// ---------------- problem constants ----------------
static constexpr int S    = 2048;
static constexpr int DH   = 64;
static constexpr int DR   = 32;
static constexpr int TILE = 128;
static constexpr int KT   = S / TILE;          // 16 key tiles per pass
static constexpr float SCALE  = 0.125f;                 // 64^-0.5
static constexpr float RSCALE = 0.17677669529663689f;   // 32^-0.5
static constexpr float LOG2E  = 1.4426950408889634f;

// padded tile layout: 128 rows x 104 halfs (96 data + 8 pad), 208B row stride
static constexpr int ROWH       = 104;
static constexpr int TILE_HALFS = TILE * ROWH;          // 13312
static constexpr int TILE_BYTES = TILE_HALFS * 2;       // 26624
static constexpr int NTILES     = 64 * 16;              // (B*H) x tiles = 1024

// scratch: pre-converted bf16 hi/lo operands (static device arrays are legal)
__device__ __align__(256) __nv_bfloat16 g_qh[(size_t)NTILES * TILE_HALFS];
__device__ __align__(256) __nv_bfloat16 g_ql[(size_t)NTILES * TILE_HALFS];
__device__ __align__(256) __nv_bfloat16 g_kh[(size_t)NTILES * TILE_HALFS];
__device__ __align__(256) __nv_bfloat16 g_kl[(size_t)NTILES * TILE_HALFS];

// ---------------- smem layout ----------------
static constexpr int SM_STAT = 0;        // 6 x 128 floats = 3072B
static constexpr int SM_AH   = 4096;
static constexpr int SM_AL   = SM_AH + TILE_BYTES;
static constexpr int SM_B0H  = SM_AL + TILE_BYTES;
static constexpr int SM_B0L  = SM_B0H + TILE_BYTES;
static constexpr int SM_B1H  = SM_B0L + TILE_BYTES;
static constexpr int SM_B1L  = SM_B1H + TILE_BYTES;
static constexpr int SMEM_TOTAL = SM_B1L + TILE_BYTES;  // 163840

// ---------------- PTX helpers (base sm_103 only: no tcgen05) ----------------
__device__ __forceinline__ uint32_t smem_u32(const void* p) {
    uint32_t a;
    asm("{ .reg .u64 t; cvta.to.shared.u64 t, %1; cvt.u32.u64 %0, t; }" : "=r"(a) : "l"(p));
    return a;
}
__device__ __forceinline__ float ex2f(float x) {
    float y; asm("ex2.approx.f32 %0, %1;" : "=f"(y) : "f"(x)); return y;
}
__device__ __forceinline__ void ldsm4(uint32_t* r, uint32_t addr) {
    asm volatile("ldmatrix.sync.aligned.m8n8.x4.shared.b16 {%0,%1,%2,%3}, [%4];"
                 : "=r"(r[0]), "=r"(r[1]), "=r"(r[2]), "=r"(r[3]) : "r"(addr));
}
__device__ __forceinline__ void mma16816(float* c, const uint32_t* a, const uint32_t* b) {
    asm volatile(
        "mma.sync.aligned.m16n8k16.row.col.f32.bf16.bf16.f32 "
        "{%0,%1,%2,%3}, {%4,%5,%6,%7}, {%8,%9}, {%0,%1,%2,%3};"
        : "+f"(c[0]), "+f"(c[1]), "+f"(c[2]), "+f"(c[3])
        : "r"(a[0]), "r"(a[1]), "r"(a[2]), "r"(a[3]), "r"(b[0]), "r"(b[1]));
}
__device__ __forceinline__ void cpa16(uint32_t daddr, const void* src) {
    asm volatile("cp.async.cg.shared.global [%0], [%1], 16;" :: "r"(daddr), "l"(src) : "memory");
}
#define CP_COMMIT() asm volatile("cp.async.commit_group;" ::: "memory")
#define CP_WAIT1()  asm volatile("cp.async.wait_group 1;" ::: "memory")
#define CP_WAIT0()  asm volatile("cp.async.wait_group 0;" ::: "memory")

// ---------------- pre-conversion kernel ----------------
// One block per (bh*S) row; converts both the Q-side row and the K-side row.
// Q side is pre-scaled by SCALE*LOG2E / RSCALE*LOG2E so scores land in log2 domain.
__global__ void __launch_bounds__(96) convert_kernel(
    const float* __restrict__ keys, const float* __restrict__ queries,
    const float* __restrict__ pos_key, const float* __restrict__ pos_query) {
    const int rg = blockIdx.x;               // bh*2048 + s
    const int j  = threadIdx.x;              // 0..95
    const size_t tile = (size_t)(rg >> 7);   // bh*16 + s/128
    const int r = rg & 127;
    const size_t off = tile * TILE_HALFS + (size_t)r * ROWH + j;

    // Q side (scaled)
    {
        float v = (j < DH) ? queries[(size_t)rg * DH + j]
                           : pos_query[(size_t)rg * DR + (j - DH)];
        float scl = (j < DH) ? (SCALE * LOG2E) : (RSCALE * LOG2E);
        float c = fminf(fmaxf(v, -5.0f), 5.0f) * scl;
        __nv_bfloat16 h = __float2bfloat16(c);
        g_qh[off] = h;
        g_ql[off] = __float2bfloat16(c - __bfloat162float(h));
    }
    // K side (unscaled)
    {
        float v = (j < DH) ? keys[(size_t)rg * DH + j]
                           : pos_key[(size_t)rg * DR + (j - DH)];
        float c = fminf(fmaxf(v, -5.0f), 5.0f);
        __nv_bfloat16 h = __float2bfloat16(c);
        g_kh[off] = h;
        g_kl[off] = __float2bfloat16(c - __bfloat162float(h));
    }
}

// ---------------- main attention-map kernel ----------------
__device__ __forceinline__ void copy_tile(uint32_t dsm, const __nv_bfloat16* src, int tid) {
    const char* s = reinterpret_cast<const char*>(src);
#pragma unroll
    for (int i = tid * 16; i < TILE_BYTES; i += 256 * 16)
        cpa16(dsm + i, s + i);
}

__global__ void __launch_bounds__(256, 1)
attnmap_kernel(float* __restrict__ out) {
    extern __shared__ char smem[];
    const int tid  = threadIdx.x;
    const int wid  = tid >> 5, lane = tid & 31;
    const int qt   = blockIdx.x;
    const int bh   = blockIdx.y;
    const uint32_t sb = smem_u32(smem);

    const int warpM = (wid >> 1) << 5;   // 0,32,64,96
    const int warpN = (wid & 1) << 6;    // 0,64

    // per-lane ldmatrix base byte-offsets within a tile buffer
    uint32_t abase[2], bbase[4];
#pragma unroll
    for (int mi = 0; mi < 2; mi++) {
        int row = warpM + mi * 16 + (lane & 15);
        abase[mi] = (uint32_t)(row * 208 + ((lane >> 4) << 4));
    }
#pragma unroll
    for (int nq = 0; nq < 4; nq++) {
        int row = warpN + nq * 16 + (lane & 7) + (((lane >> 4) & 1) << 3);
        bbase[nq] = (uint32_t)(row * 208 + (((lane >> 3) & 1) << 4));
    }

    const __nv_bfloat16* qh = g_qh + (size_t)(bh * 16 + qt) * TILE_HALFS;
    const __nv_bfloat16* ql = g_ql + (size_t)(bh * 16 + qt) * TILE_HALFS;
    const __nv_bfloat16* khb = g_kh + (size_t)(bh * 16) * TILE_HALFS;
    const __nv_bfloat16* klb = g_kl + (size_t)(bh * 16) * TILE_HALFS;

    // prologue: A tiles (group 1), key-tile 0 (group 2)
    copy_tile(sb + SM_AH, qh, tid);
    copy_tile(sb + SM_AL, ql, tid);
    CP_COMMIT();
    copy_tile(sb + SM_B0H, khb, tid);
    copy_tile(sb + SM_B0L, klb, tid);
    CP_COMMIT();

    float* st_m0 = reinterpret_cast<float*>(smem + SM_STAT);
    float* st_l0 = st_m0 + 128;
    float* st_m1 = st_m0 + 256;
    float* st_l1 = st_m0 + 384;
    float* st_M  = st_m0 + 512;
    float* st_I  = st_m0 + 640;

    float m2[4], l2[4], Ms[4] = {0, 0, 0, 0}, Is[4] = {0, 0, 0, 0};
#pragma unroll
    for (int sl = 0; sl < 4; sl++) { m2[sl] = -1e30f; l2[sl] = 0.0f; }

    for (int gt = 0; gt < 2 * KT; gt++) {
        const int kt = gt & 15;
        __syncthreads();    // prior compute done before overwriting prefetch buffer
        if (gt + 1 < 2 * KT) {
            const int ktn = (gt + 1) & 15;
            const int nb = (gt + 1) & 1;
            copy_tile(sb + (nb ? SM_B1H : SM_B0H), khb + (size_t)ktn * TILE_HALFS, tid);
            copy_tile(sb + (nb ? SM_B1L : SM_B0L), klb + (size_t)ktn * TILE_HALFS, tid);
            CP_COMMIT();
            CP_WAIT1();
        } else {
            CP_WAIT0();
        }
        __syncthreads();    // current tile visible to all warps

        const uint32_t sAh = sb + SM_AH, sAl = sb + SM_AL;
        const uint32_t sBh = sb + ((gt & 1) ? SM_B1H : SM_B0H);
        const uint32_t sBl = sb + ((gt & 1) ? SM_B1L : SM_B0L);

        float c[2][8][4];
#pragma unroll
        for (int mi = 0; mi < 2; mi++)
#pragma unroll
            for (int ni = 0; ni < 8; ni++)
#pragma unroll
                for (int j = 0; j < 4; j++) c[mi][ni][j] = 0.0f;

#pragma unroll
        for (int ks = 0; ks < 6; ks++) {
            const uint32_t ko = (uint32_t)(ks * 32);
            uint32_t ah[2][4], al[2][4];
            ldsm4(ah[0], sAh + abase[0] + ko);
            ldsm4(ah[1], sAh + abase[1] + ko);
            ldsm4(al[0], sAl + abase[0] + ko);
            ldsm4(al[1], sAl + abase[1] + ko);
#pragma unroll
            for (int nq = 0; nq < 4; nq++) {
                uint32_t bh4[4], bl4[4];
                ldsm4(bh4, sBh + bbase[nq] + ko);
                ldsm4(bl4, sBl + bbase[nq] + ko);
#pragma unroll
                for (int mi = 0; mi < 2; mi++) {
#pragma unroll
                    for (int nb = 0; nb < 2; nb++) {
                        const int ni = nq * 2 + nb;
                        mma16816(c[mi][ni], ah[mi], &bh4[nb * 2]);   // Ah*Bh
                        mma16816(c[mi][ni], al[mi], &bh4[nb * 2]);   // Al*Bh
                        mma16816(c[mi][ni], ah[mi], &bl4[nb * 2]);   // Ah*Bl
                    }
                }
            }
        }

        if (gt < KT) {
            // ---- pass 1: online row stats (scores already in log2 domain) ----
#pragma unroll
            for (int mi = 0; mi < 2; mi++) {
#pragma unroll
                for (int rh = 0; rh < 2; rh++) {
                    const int sl = mi * 2 + rh;
                    float cm = -1e30f;
#pragma unroll
                    for (int ni = 0; ni < 8; ni++)
                        cm = fmaxf(cm, fmaxf(c[mi][ni][rh * 2], c[mi][ni][rh * 2 + 1]));
                    const float mn = fmaxf(m2[sl], cm);
                    const float corr = ex2f(m2[sl] - mn);
                    float acc = 0.0f;
#pragma unroll
                    for (int ni = 0; ni < 8; ni++)
                        acc += ex2f(c[mi][ni][rh * 2] - mn) + ex2f(c[mi][ni][rh * 2 + 1] - mn);
                    l2[sl] = l2[sl] * corr + acc;
                    m2[sl] = mn;
                }
            }
            if (gt == KT - 1) {
                // lane reduction over the 4 lanes sharing each row
#pragma unroll
                for (int d = 1; d <= 2; d <<= 1) {
#pragma unroll
                    for (int sl = 0; sl < 4; sl++) {
                        const float mo = __shfl_xor_sync(0xFFFFFFFFu, m2[sl], d);
                        const float lo = __shfl_xor_sync(0xFFFFFFFFu, l2[sl], d);
                        const float mn = fmaxf(m2[sl], mo);
                        l2[sl] = l2[sl] * ex2f(m2[sl] - mn) + lo * ex2f(mo - mn);
                        m2[sl] = mn;
                    }
                }
                if ((lane & 3) == 0) {
#pragma unroll
                    for (int sl = 0; sl < 4; sl++) {
                        const int row = warpM + (sl >> 1) * 16 + (sl & 1) * 8 + (lane >> 2);
                        if ((wid & 1) == 0) { st_m0[row] = m2[sl]; st_l0[row] = l2[sl]; }
                        else                { st_m1[row] = m2[sl]; st_l1[row] = l2[sl]; }
                    }
                }
                __syncthreads();
                if (tid < 128) {
                    const float ma = st_m0[tid], mb = st_m1[tid];
                    const float Mx = fmaxf(ma, mb);
                    const float L = st_l0[tid] * ex2f(ma - Mx) + st_l1[tid] * ex2f(mb - Mx);
                    st_M[tid] = Mx;
                    st_I[tid] = 1.0f / L;
                }
                __syncthreads();
#pragma unroll
                for (int sl = 0; sl < 4; sl++) {
                    const int row = warpM + (sl >> 1) * 16 + (sl & 1) * 8 + (lane >> 2);
                    Ms[sl] = st_M[row];
                    Is[sl] = st_I[row];
                }
            }
        } else {
            // ---- pass 2: normalize + store ----
#pragma unroll
            for (int mi = 0; mi < 2; mi++) {
                const int rbase = qt * TILE + warpM + mi * 16 + (lane >> 2);
                const float M0 = Ms[mi * 2], I0 = Is[mi * 2];
                const float M1 = Ms[mi * 2 + 1], I1 = Is[mi * 2 + 1];
                float* o0 = out + ((size_t)(bh * S + rbase) * S) + (size_t)(kt * TILE + warpN) + ((lane & 3) << 1);
                float* o1 = o0 + 8 * (size_t)S;
#pragma unroll
                for (int ni = 0; ni < 8; ni++) {
                    float2 v0, v1;
                    v0.x = ex2f(c[mi][ni][0] - M0) * I0;
                    v0.y = ex2f(c[mi][ni][1] - M0) * I0;
                    v1.x = ex2f(c[mi][ni][2] - M1) * I1;
                    v1.y = ex2f(c[mi][ni][3] - M1) * I1;
                    reinterpret_cast<float2*>(o0)[ni * 4] = v0;   // ni*8 floats = ni*4 float2
                    reinterpret_cast<float2*>(o1)[ni * 4] = v1;
                }
            }
        }
    }
}

// ---------------- launch ----------------
extern "C" void kernel_launch(void* const* d_in, const int* in_sizes, int n_in,
                              void* d_out, int out_size) {
    (void)in_sizes; (void)n_in; (void)out_size;
    const float* keys      = (const float*)d_in[0];
    const float* queries   = (const float*)d_in[1];
    const float* pos_key   = (const float*)d_in[2];
    const float* pos_query = (const float*)d_in[3];
    float* out = (float*)d_out;

    convert_kernel<<<64 * S, 96>>>(keys, queries, pos_key, pos_query);

    cudaFuncSetAttribute(attnmap_kernel, cudaFuncAttributeMaxDynamicSharedMemorySize, SMEM_TOTAL);
    dim3 grid(S / TILE, 64, 1);
    attnmap_kernel<<<grid, 256, SMEM_TOTAL>>>(out);
}

// round 3
// speedup vs baseline: 1.4855x; 1.4855x over previous
#include <cuda_runtime.h>
#include <cuda_fp16.h>
#include <cstdint>
#include <cstddef>

// ---------------- problem constants ----------------
static constexpr int S    = 2048;
static constexpr int DH   = 64;
static constexpr int DR   = 32;
static constexpr int TILE = 128;
static constexpr int KT   = S / TILE;          // 16 key tiles per pass
static constexpr float SCALE  = 0.125f;                 // 64^-0.5
static constexpr float RSCALE = 0.17677669529663689f;   // 32^-0.5
static constexpr float LOG2E  = 1.4426950408889634f;

// padded tile layout: 128 rows x 104 halfs (96 data + 8 pad), 208B row stride
static constexpr int ROWH       = 104;
static constexpr int TILE_HALFS = TILE * ROWH;          // 13312
static constexpr int TILE_BYTES = TILE_HALFS * 2;       // 26624
static constexpr int NTILES     = 64 * 16;              // (B*H) x tiles = 1024

// scratch: pre-converted fp16 operands.
// Q side split hi/lo (A exact to ~2^-21); K side single fp16 (err 2^-12 RMS).
__device__ __align__(256) __half g_qh[(size_t)NTILES * TILE_HALFS];
__device__ __align__(256) __half g_ql[(size_t)NTILES * TILE_HALFS];
__device__ __align__(256) __half g_kh[(size_t)NTILES * TILE_HALFS];

// ---------------- smem layout ----------------
static constexpr int SM_STAT = 0;        // 6 x 128 floats = 3072B
static constexpr int SM_AH   = 4096;
static constexpr int SM_AL   = SM_AH + TILE_BYTES;
static constexpr int SM_B0   = SM_AL + TILE_BYTES;
static constexpr int SM_B1   = SM_B0 + TILE_BYTES;
static constexpr int SMEM_TOTAL = SM_B1 + TILE_BYTES;   // 110592 -> 2 CTAs/SM

// ---------------- PTX helpers (base sm_103: no tcgen05 available) ----------------
__device__ __forceinline__ uint32_t smem_u32(const void* p) {
    uint32_t a;
    asm("{ .reg .u64 t; cvta.to.shared.u64 t, %1; cvt.u32.u64 %0, t; }" : "=r"(a) : "l"(p));
    return a;
}
__device__ __forceinline__ float ex2f(float x) {
    float y; asm("ex2.approx.f32 %0, %1;" : "=f"(y) : "f"(x)); return y;
}
__device__ __forceinline__ void ldsm4(uint32_t* r, uint32_t addr) {
    asm volatile("ldmatrix.sync.aligned.m8n8.x4.shared.b16 {%0,%1,%2,%3}, [%4];"
                 : "=r"(r[0]), "=r"(r[1]), "=r"(r[2]), "=r"(r[3]) : "r"(addr));
}
__device__ __forceinline__ void mma16816(float* c, const uint32_t* a, const uint32_t* b) {
    asm volatile(
        "mma.sync.aligned.m16n8k16.row.col.f32.f16.f16.f32 "
        "{%0,%1,%2,%3}, {%4,%5,%6,%7}, {%8,%9}, {%0,%1,%2,%3};"
        : "+f"(c[0]), "+f"(c[1]), "+f"(c[2]), "+f"(c[3])
        : "r"(a[0]), "r"(a[1]), "r"(a[2]), "r"(a[3]), "r"(b[0]), "r"(b[1]));
}
__device__ __forceinline__ void cpa16(uint32_t daddr, const void* src) {
    asm volatile("cp.async.cg.shared.global [%0], [%1], 16;" :: "r"(daddr), "l"(src) : "memory");
}
#define CP_COMMIT() asm volatile("cp.async.commit_group;" ::: "memory")
#define CP_WAIT1()  asm volatile("cp.async.wait_group 1;" ::: "memory")
#define CP_WAIT0()  asm volatile("cp.async.wait_group 0;" ::: "memory")

// ---------------- pre-conversion kernel ----------------
// 384 threads = 4 rows x 96 cols. Q side pre-scaled by SCALE*LOG2E / RSCALE*LOG2E
// so scores land directly in the log2 domain.
__global__ void __launch_bounds__(384) convert_kernel(
    const float* __restrict__ keys, const float* __restrict__ queries,
    const float* __restrict__ pos_key, const float* __restrict__ pos_query) {
    const int rg = blockIdx.x * 4 + threadIdx.x / 96;   // bh*2048 + s
    const int j  = threadIdx.x % 96;
    const size_t tile = (size_t)(rg >> 7);              // bh*16 + s/128
    const int r = rg & 127;
    const size_t off = tile * TILE_HALFS + (size_t)r * ROWH + j;

    // Q side (scaled, hi/lo split)
    {
        float v = (j < DH) ? queries[(size_t)rg * DH + j]
                           : pos_query[(size_t)rg * DR + (j - DH)];
        float scl = (j < DH) ? (SCALE * LOG2E) : (RSCALE * LOG2E);
        float c = fminf(fmaxf(v, -5.0f), 5.0f) * scl;
        __half h = __float2half_rn(c);
        g_qh[off] = h;
        g_ql[off] = __float2half_rn(c - __half2float(h));
    }
    // K side (unscaled, single fp16)
    {
        float v = (j < DH) ? keys[(size_t)rg * DH + j]
                           : pos_key[(size_t)rg * DR + (j - DH)];
        g_kh[off] = __float2half_rn(fminf(fmaxf(v, -5.0f), 5.0f));
    }
}

// ---------------- main attention-map kernel ----------------
__device__ __forceinline__ void copy_tile(uint32_t dsm, const __half* src, int tid) {
    const char* s = reinterpret_cast<const char*>(src);
#pragma unroll
    for (int i = tid * 16; i < TILE_BYTES; i += 256 * 16)
        cpa16(dsm + i, s + i);
}

__global__ void __launch_bounds__(256, 2)
attnmap_kernel(float* __restrict__ out) {
    extern __shared__ char smem[];
    const int tid  = threadIdx.x;
    const int wid  = tid >> 5, lane = tid & 31;
    const int qt   = blockIdx.x;
    const int bh   = blockIdx.y;
    const uint32_t sb = smem_u32(smem);

    const int warpM = (wid >> 1) << 5;   // 0,32,64,96
    const int warpN = (wid & 1) << 6;    // 0,64

    // per-lane ldmatrix base byte-offsets within a tile buffer
    uint32_t abase[2], bbase[4];
#pragma unroll
    for (int mi = 0; mi < 2; mi++) {
        int row = warpM + mi * 16 + (lane & 15);
        abase[mi] = (uint32_t)(row * 208 + ((lane >> 4) << 4));
    }
#pragma unroll
    for (int nq = 0; nq < 4; nq++) {
        int row = warpN + nq * 16 + (lane & 7) + (((lane >> 4) & 1) << 3);
        bbase[nq] = (uint32_t)(row * 208 + (((lane >> 3) & 1) << 4));
    }

    const __half* qh  = g_qh + (size_t)(bh * 16 + qt) * TILE_HALFS;
    const __half* ql  = g_ql + (size_t)(bh * 16 + qt) * TILE_HALFS;
    const __half* khb = g_kh + (size_t)(bh * 16) * TILE_HALFS;

    // prologue: A tiles (group 1), key-tile 0 (group 2)
    copy_tile(sb + SM_AH, qh, tid);
    copy_tile(sb + SM_AL, ql, tid);
    CP_COMMIT();
    copy_tile(sb + SM_B0, khb, tid);
    CP_COMMIT();

    float* st_m0 = reinterpret_cast<float*>(smem + SM_STAT);
    float* st_l0 = st_m0 + 128;
    float* st_m1 = st_m0 + 256;
    float* st_l1 = st_m0 + 384;
    float* st_M  = st_m0 + 512;
    float* st_I  = st_m0 + 640;

    float m2[4], l2[4], Ms[4] = {0, 0, 0, 0}, Is[4] = {0, 0, 0, 0};
#pragma unroll
    for (int sl = 0; sl < 4; sl++) { m2[sl] = -1e30f; l2[sl] = 0.0f; }

    for (int gt = 0; gt < 2 * KT; gt++) {
        const int kt = gt & 15;
        __syncthreads();    // prior compute done before overwriting prefetch buffer
        if (gt + 1 < 2 * KT) {
            const int ktn = (gt + 1) & 15;
            copy_tile(sb + (((gt + 1) & 1) ? SM_B1 : SM_B0),
                      khb + (size_t)ktn * TILE_HALFS, tid);
            CP_COMMIT();
            CP_WAIT1();
        } else {
            CP_WAIT0();
        }
        __syncthreads();    // current tile visible to all warps

        const uint32_t sAh = sb + SM_AH, sAl = sb + SM_AL;
        const uint32_t sB  = sb + ((gt & 1) ? SM_B1 : SM_B0);

        float c[2][8][4];
#pragma unroll
        for (int mi = 0; mi < 2; mi++)
#pragma unroll
            for (int ni = 0; ni < 8; ni++)
#pragma unroll
                for (int j = 0; j < 4; j++) c[mi][ni][j] = 0.0f;

#pragma unroll
        for (int ks = 0; ks < 6; ks++) {
            const uint32_t ko = (uint32_t)(ks * 32);
            uint32_t ah[2][4], al[2][4];
            ldsm4(ah[0], sAh + abase[0] + ko);
            ldsm4(ah[1], sAh + abase[1] + ko);
            ldsm4(al[0], sAl + abase[0] + ko);
            ldsm4(al[1], sAl + abase[1] + ko);
#pragma unroll
            for (int nq = 0; nq < 4; nq++) {
                uint32_t b4[4];
                ldsm4(b4, sB + bbase[nq] + ko);
#pragma unroll
                for (int mi = 0; mi < 2; mi++) {
#pragma unroll
                    for (int nb = 0; nb < 2; nb++) {
                        const int ni = nq * 2 + nb;
                        mma16816(c[mi][ni], ah[mi], &b4[nb * 2]);   // Ah*B
                        mma16816(c[mi][ni], al[mi], &b4[nb * 2]);   // Al*B
                    }
                }
            }
        }

        if (gt < KT) {
            // ---- pass 1: online row stats (scores already in log2 domain) ----
#pragma unroll
            for (int mi = 0; mi < 2; mi++) {
#pragma unroll
                for (int rh = 0; rh < 2; rh++) {
                    const int sl = mi * 2 + rh;
                    float cm = -1e30f;
#pragma unroll
                    for (int ni = 0; ni < 8; ni++)
                        cm = fmaxf(cm, fmaxf(c[mi][ni][rh * 2], c[mi][ni][rh * 2 + 1]));
                    const float mn = fmaxf(m2[sl], cm);
                    const float corr = ex2f(m2[sl] - mn);
                    float acc = 0.0f;
#pragma unroll
                    for (int ni = 0; ni < 8; ni++)
                        acc += ex2f(c[mi][ni][rh * 2] - mn) + ex2f(c[mi][ni][rh * 2 + 1] - mn);
                    l2[sl] = l2[sl] * corr + acc;
                    m2[sl] = mn;
                }
            }
            if (gt == KT - 1) {
                // lane reduction over the 4 lanes sharing each row
#pragma unroll
                for (int d = 1; d <= 2; d <<= 1) {
#pragma unroll
                    for (int sl = 0; sl < 4; sl++) {
                        const float mo = __shfl_xor_sync(0xFFFFFFFFu, m2[sl], d);
                        const float lo = __shfl_xor_sync(0xFFFFFFFFu, l2[sl], d);
                        const float mn = fmaxf(m2[sl], mo);
                        l2[sl] = l2[sl] * ex2f(m2[sl] - mn) + lo * ex2f(mo - mn);
                        m2[sl] = mn;
                    }
                }
                if ((lane & 3) == 0) {
#pragma unroll
                    for (int sl = 0; sl < 4; sl++) {
                        const int row = warpM + (sl >> 1) * 16 + (sl & 1) * 8 + (lane >> 2);
                        if ((wid & 1) == 0) { st_m0[row] = m2[sl]; st_l0[row] = l2[sl]; }
                        else                { st_m1[row] = m2[sl]; st_l1[row] = l2[sl]; }
                    }
                }
                __syncthreads();
                if (tid < 128) {
                    const float ma = st_m0[tid], mb = st_m1[tid];
                    const float Mx = fmaxf(ma, mb);
                    const float L = st_l0[tid] * ex2f(ma - Mx) + st_l1[tid] * ex2f(mb - Mx);
                    st_M[tid] = Mx;
                    st_I[tid] = 1.0f / L;
                }
                __syncthreads();
#pragma unroll
                for (int sl = 0; sl < 4; sl++) {
                    const int row = warpM + (sl >> 1) * 16 + (sl & 1) * 8 + (lane >> 2);
                    Ms[sl] = st_M[row];
                    Is[sl] = st_I[row];
                }
            }
        } else {
            // ---- pass 2: normalize + store ----
#pragma unroll
            for (int mi = 0; mi < 2; mi++) {
                const int rbase = qt * TILE + warpM + mi * 16 + (lane >> 2);
                const float M0 = Ms[mi * 2], I0 = Is[mi * 2];
                const float M1 = Ms[mi * 2 + 1], I1 = Is[mi * 2 + 1];
                float* o0 = out + ((size_t)(bh * S + rbase) * S) + (size_t)(kt * TILE + warpN) + ((lane & 3) << 1);
                float* o1 = o0 + 8 * (size_t)S;
#pragma unroll
                for (int ni = 0; ni < 8; ni++) {
                    float2 v0, v1;
                    v0.x = ex2f(c[mi][ni][0] - M0) * I0;
                    v0.y = ex2f(c[mi][ni][1] - M0) * I0;
                    v1.x = ex2f(c[mi][ni][2] - M1) * I1;
                    v1.y = ex2f(c[mi][ni][3] - M1) * I1;
                    reinterpret_cast<float2*>(o0)[ni * 4] = v0;
                    reinterpret_cast<float2*>(o1)[ni * 4] = v1;
                }
            }
        }
    }
}

// ---------------- launch ----------------
extern "C" void kernel_launch(void* const* d_in, const int* in_sizes, int n_in,
                              void* d_out, int out_size) {
    (void)in_sizes; (void)n_in; (void)out_size;
    const float* keys      = (const float*)d_in[0];
    const float* queries   = (const float*)d_in[1];
    const float* pos_key   = (const float*)d_in[2];
    const float* pos_query = (const float*)d_in[3];
    float* out = (float*)d_out;

    convert_kernel<<<64 * S / 4, 384>>>(keys, queries, pos_key, pos_query);

    cudaFuncSetAttribute(attnmap_kernel, cudaFuncAttributeMaxDynamicSharedMemorySize, SMEM_TOTAL);
    dim3 grid(S / TILE, 64, 1);
    attnmap_kernel<<<grid, 256, SMEM_TOTAL>>>(out);
}

// round 4
// speedup vs baseline: 2.0636x; 1.3892x over previous
#include <cuda_runtime.h>
#include <cuda_fp16.h>
#include <cstdint>
#include <cstddef>

// ---------------- problem constants ----------------
static constexpr int S    = 2048;
static constexpr int DH   = 64;
static constexpr int DR   = 32;
static constexpr int TILE = 128;
static constexpr int KT   = S / TILE;          // 16 key tiles per pass
static constexpr float SCALE  = 0.125f;                 // 64^-0.5
static constexpr float RSCALE = 0.17677669529663689f;   // 32^-0.5
static constexpr float LOG2E  = 1.4426950408889634f;

// padded tile layout: 128 rows x 104 halfs (96 data + 8 pad), 208B row stride
static constexpr int ROWH       = 104;
static constexpr int TILE_HALFS = TILE * ROWH;          // 13312
static constexpr int TILE_BYTES = TILE_HALFS * 2;       // 26624
static constexpr int NTILES     = 64 * 16;              // (B*H) x tiles = 1024

// scratch: pre-converted fp16 operands (single-term: both sides rounded once).
__device__ __align__(256) __half g_qh[(size_t)NTILES * TILE_HALFS];
__device__ __align__(256) __half g_kh[(size_t)NTILES * TILE_HALFS];

// ---------------- smem layout ----------------
static constexpr int SM_STAT = 0;        // 6 x 128 floats = 3072B
static constexpr int SM_AH   = 4096;
static constexpr int SM_B0   = SM_AH + TILE_BYTES;
static constexpr int SM_B1   = SM_B0 + TILE_BYTES;
static constexpr int SMEM_TOTAL = SM_B1 + TILE_BYTES;   // 83968 -> 2 CTAs/SM

// ---------------- PTX helpers (base sm_103: no tcgen05 available) ----------------
__device__ __forceinline__ uint32_t smem_u32(const void* p) {
    uint32_t a;
    asm("{ .reg .u64 t; cvta.to.shared.u64 t, %1; cvt.u32.u64 %0, t; }" : "=r"(a) : "l"(p));
    return a;
}
__device__ __forceinline__ float ex2f(float x) {
    float y; asm("ex2.approx.f32 %0, %1;" : "=f"(y) : "f"(x)); return y;
}
__device__ __forceinline__ void ldsm4(uint32_t* r, uint32_t addr) {
    asm volatile("ldmatrix.sync.aligned.m8n8.x4.shared.b16 {%0,%1,%2,%3}, [%4];"
                 : "=r"(r[0]), "=r"(r[1]), "=r"(r[2]), "=r"(r[3]) : "r"(addr));
}
__device__ __forceinline__ void mma16816(float* c, const uint32_t* a, const uint32_t* b) {
    asm volatile(
        "mma.sync.aligned.m16n8k16.row.col.f32.f16.f16.f32 "
        "{%0,%1,%2,%3}, {%4,%5,%6,%7}, {%8,%9}, {%0,%1,%2,%3};"
        : "+f"(c[0]), "+f"(c[1]), "+f"(c[2]), "+f"(c[3])
        : "r"(a[0]), "r"(a[1]), "r"(a[2]), "r"(a[3]), "r"(b[0]), "r"(b[1]));
}
__device__ __forceinline__ void cpa16(uint32_t daddr, const void* src) {
    asm volatile("cp.async.cg.shared.global [%0], [%1], 16;" :: "r"(daddr), "l"(src) : "memory");
}
#define CP_COMMIT() asm volatile("cp.async.commit_group;" ::: "memory")
#define CP_WAIT1()  asm volatile("cp.async.wait_group 1;" ::: "memory")
#define CP_WAIT0()  asm volatile("cp.async.wait_group 0;" ::: "memory")

// ---------------- pre-conversion kernel ----------------
// 384 threads = 4 rows x 96 cols. Q side pre-scaled by SCALE*LOG2E / RSCALE*LOG2E
// so scores land directly in the log2 domain.
__global__ void __launch_bounds__(384) convert_kernel(
    const float* __restrict__ keys, const float* __restrict__ queries,
    const float* __restrict__ pos_key, const float* __restrict__ pos_query) {
    const int rg = blockIdx.x * 4 + threadIdx.x / 96;   // bh*2048 + s
    const int j  = threadIdx.x % 96;
    const size_t tile = (size_t)(rg >> 7);              // bh*16 + s/128
    const int r = rg & 127;
    const size_t off = tile * TILE_HALFS + (size_t)r * ROWH + j;

    // Q side (scaled)
    {
        float v = (j < DH) ? queries[(size_t)rg * DH + j]
                           : pos_query[(size_t)rg * DR + (j - DH)];
        float scl = (j < DH) ? (SCALE * LOG2E) : (RSCALE * LOG2E);
        float c = fminf(fmaxf(v, -5.0f), 5.0f) * scl;
        g_qh[off] = __float2half_rn(c);
    }
    // K side (unscaled)
    {
        float v = (j < DH) ? keys[(size_t)rg * DH + j]
                           : pos_key[(size_t)rg * DR + (j - DH)];
        g_kh[off] = __float2half_rn(fminf(fmaxf(v, -5.0f), 5.0f));
    }
}

// ---------------- main attention-map kernel ----------------
__device__ __forceinline__ void copy_tile(uint32_t dsm, const __half* src, int tid) {
    const char* s = reinterpret_cast<const char*>(src);
#pragma unroll
    for (int i = tid * 16; i < TILE_BYTES; i += 256 * 16)
        cpa16(dsm + i, s + i);
}

__global__ void __launch_bounds__(256, 2)
attnmap_kernel(float* __restrict__ out) {
    extern __shared__ char smem[];
    const int tid  = threadIdx.x;
    const int wid  = tid >> 5, lane = tid & 31;
    const int qt   = blockIdx.x;
    const int bh   = blockIdx.y;
    const uint32_t sb = smem_u32(smem);

    const int warpM = (wid >> 1) << 5;   // 0,32,64,96
    const int warpN = (wid & 1) << 6;    // 0,64

    // per-lane ldmatrix base byte-offsets within a tile buffer
    uint32_t abase[2], bbase[4];
#pragma unroll
    for (int mi = 0; mi < 2; mi++) {
        int row = warpM + mi * 16 + (lane & 15);
        abase[mi] = (uint32_t)(row * 208 + ((lane >> 4) << 4));
    }
#pragma unroll
    for (int nq = 0; nq < 4; nq++) {
        int row = warpN + nq * 16 + (lane & 7) + (((lane >> 4) & 1) << 3);
        bbase[nq] = (uint32_t)(row * 208 + (((lane >> 3) & 1) << 4));
    }

    const __half* qh  = g_qh + (size_t)(bh * 16 + qt) * TILE_HALFS;
    const __half* khb = g_kh + (size_t)(bh * 16) * TILE_HALFS;

    // prologue: A tile (group 1), key-tile 0 (group 2)
    copy_tile(sb + SM_AH, qh, tid);
    CP_COMMIT();
    copy_tile(sb + SM_B0, khb, tid);
    CP_COMMIT();

    float* st_m0 = reinterpret_cast<float*>(smem + SM_STAT);
    float* st_l0 = st_m0 + 128;
    float* st_m1 = st_m0 + 256;
    float* st_l1 = st_m0 + 384;
    float* st_M  = st_m0 + 512;
    float* st_I  = st_m0 + 640;

    float m2[4], l2[4], Ms[4] = {0, 0, 0, 0}, Is[4] = {0, 0, 0, 0};
#pragma unroll
    for (int sl = 0; sl < 4; sl++) { m2[sl] = -1e30f; l2[sl] = 0.0f; }

    for (int gt = 0; gt < 2 * KT; gt++) {
        const int kt = gt & 15;
        __syncthreads();    // prior compute done before overwriting prefetch buffer
        if (gt + 1 < 2 * KT) {
            const int ktn = (gt + 1) & 15;
            copy_tile(sb + (((gt + 1) & 1) ? SM_B1 : SM_B0),
                      khb + (size_t)ktn * TILE_HALFS, tid);
            CP_COMMIT();
            CP_WAIT1();
        } else {
            CP_WAIT0();
        }
        __syncthreads();    // current tile visible to all warps

        const uint32_t sAh = sb + SM_AH;
        const uint32_t sB  = sb + ((gt & 1) ? SM_B1 : SM_B0);

        float c[2][8][4];
#pragma unroll
        for (int mi = 0; mi < 2; mi++)
#pragma unroll
            for (int ni = 0; ni < 8; ni++)
#pragma unroll
                for (int j = 0; j < 4; j++) c[mi][ni][j] = 0.0f;

#pragma unroll
        for (int ks = 0; ks < 6; ks++) {
            const uint32_t ko = (uint32_t)(ks * 32);
            uint32_t ah[2][4];
            ldsm4(ah[0], sAh + abase[0] + ko);
            ldsm4(ah[1], sAh + abase[1] + ko);
#pragma unroll
            for (int nq = 0; nq < 4; nq++) {
                uint32_t b4[4];
                ldsm4(b4, sB + bbase[nq] + ko);
#pragma unroll
                for (int mi = 0; mi < 2; mi++) {
#pragma unroll
                    for (int nb = 0; nb < 2; nb++) {
                        const int ni = nq * 2 + nb;
                        mma16816(c[mi][ni], ah[mi], &b4[nb * 2]);
                    }
                }
            }
        }

        if (gt < KT) {
            // ---- pass 1: online row stats (scores already in log2 domain) ----
#pragma unroll
            for (int mi = 0; mi < 2; mi++) {
#pragma unroll
                for (int rh = 0; rh < 2; rh++) {
                    const int sl = mi * 2 + rh;
                    float cm = -1e30f;
#pragma unroll
                    for (int ni = 0; ni < 8; ni++)
                        cm = fmaxf(cm, fmaxf(c[mi][ni][rh * 2], c[mi][ni][rh * 2 + 1]));
                    const float mn = fmaxf(m2[sl], cm);
                    const float corr = ex2f(m2[sl] - mn);
                    float acc = 0.0f;
#pragma unroll
                    for (int ni = 0; ni < 8; ni++)
                        acc += ex2f(c[mi][ni][rh * 2] - mn) + ex2f(c[mi][ni][rh * 2 + 1] - mn);
                    l2[sl] = l2[sl] * corr + acc;
                    m2[sl] = mn;
                }
            }
            if (gt == KT - 1) {
                // lane reduction over the 4 lanes sharing each row
#pragma unroll
                for (int d = 1; d <= 2; d <<= 1) {
#pragma unroll
                    for (int sl = 0; sl < 4; sl++) {
                        const float mo = __shfl_xor_sync(0xFFFFFFFFu, m2[sl], d);
                        const float lo = __shfl_xor_sync(0xFFFFFFFFu, l2[sl], d);
                        const float mn = fmaxf(m2[sl], mo);
                        l2[sl] = l2[sl] * ex2f(m2[sl] - mn) + lo * ex2f(mo - mn);
                        m2[sl] = mn;
                    }
                }
                if ((lane & 3) == 0) {
#pragma unroll
                    for (int sl = 0; sl < 4; sl++) {
                        const int row = warpM + (sl >> 1) * 16 + (sl & 1) * 8 + (lane >> 2);
                        if ((wid & 1) == 0) { st_m0[row] = m2[sl]; st_l0[row] = l2[sl]; }
                        else                { st_m1[row] = m2[sl]; st_l1[row] = l2[sl]; }
                    }
                }
                __syncthreads();
                if (tid < 128) {
                    const float ma = st_m0[tid], mb = st_m1[tid];
                    const float Mx = fmaxf(ma, mb);
                    const float L = st_l0[tid] * ex2f(ma - Mx) + st_l1[tid] * ex2f(mb - Mx);
                    st_M[tid] = Mx;
                    st_I[tid] = 1.0f / L;
                }
                __syncthreads();
#pragma unroll
                for (int sl = 0; sl < 4; sl++) {
                    const int row = warpM + (sl >> 1) * 16 + (sl & 1) * 8 + (lane >> 2);
                    Ms[sl] = st_M[row];
                    Is[sl] = st_I[row];
                }
            }
        } else {
            // ---- pass 2: normalize + store ----
#pragma unroll
            for (int mi = 0; mi < 2; mi++) {
                const int rbase = qt * TILE + warpM + mi * 16 + (lane >> 2);
                const float M0 = Ms[mi * 2], I0 = Is[mi * 2];
                const float M1 = Ms[mi * 2 + 1], I1 = Is[mi * 2 + 1];
                float* o0 = out + ((size_t)(bh * S + rbase) * S) + (size_t)(kt * TILE + warpN) + ((lane & 3) << 1);
                float* o1 = o0 + 8 * (size_t)S;
#pragma unroll
                for (int ni = 0; ni < 8; ni++) {
                    float2 v0, v1;
                    v0.x = ex2f(c[mi][ni][0] - M0) * I0;
                    v0.y = ex2f(c[mi][ni][1] - M0) * I0;
                    v1.x = ex2f(c[mi][ni][2] - M1) * I1;
                    v1.y = ex2f(c[mi][ni][3] - M1) * I1;
                    reinterpret_cast<float2*>(o0)[ni * 4] = v0;
                    reinterpret_cast<float2*>(o1)[ni * 4] = v1;
                }
            }
        }
    }
}

// ---------------- launch ----------------
extern "C" void kernel_launch(void* const* d_in, const int* in_sizes, int n_in,
                              void* d_out, int out_size) {
    (void)in_sizes; (void)n_in; (void)out_size;
    const float* keys      = (const float*)d_in[0];
    const float* queries   = (const float*)d_in[1];
    const float* pos_key   = (const float*)d_in[2];
    const float* pos_query = (const float*)d_in[3];
    float* out = (float*)d_out;

    convert_kernel<<<64 * S / 4, 384>>>(keys, queries, pos_key, pos_query);

    cudaFuncSetAttribute(attnmap_kernel, cudaFuncAttributeMaxDynamicSharedMemorySize, SMEM_TOTAL);
    dim3 grid(S / TILE, 64, 1);
    attnmap_kernel<<<grid, 256, SMEM_TOTAL>>>(out);
}